// round 1
// baseline (speedup 1.0000x reference)
#include <cuda_runtime.h>
#include <cuda_bf16.h>
#include <cstdint>

// Problem constants (fixed by the dataset)
#define BS 8
#define NQ 2048
#define MP 64
#define DD 1024

// Main-kernel tiling
#define KC 32                 // K-chunk (elements of d) per smem stage
#define ASTRIDE 40            // KC + 8 pad (bf16 elems) -> conflict-free frag LDS
#define NROWS 128             // CTA rows (N tile)

// __device__ scratch (allocation-free rule: no cudaMalloc anywhere)
__device__ __nv_bfloat16 g_B1[BS * MP * DD];   // mask^2            (bf16)
__device__ __nv_bfloat16 g_B2[BS * MP * DD];   // -2 * mask^2 * p   (bf16)
__device__ float         g_pterm[BS * MP];     // sum_d (mask*p)^2  (fp32)

// ---------------------------------------------------------------------------
// Prep: build bf16 B-matrices and pterm. grid = BS*MP blocks, 256 threads.
// ---------------------------------------------------------------------------
__global__ void proto_prep_kernel(const float* __restrict__ proto,
                                  const float* __restrict__ mask) {
    const int bm = blockIdx.x;          // 0..511  (b*MP + m)
    const int t  = threadIdx.x;         // 256 threads
    const float* mrow = mask  + (size_t)bm * DD;
    const float* prow = proto + (size_t)bm * DD;

    float psum = 0.f;
    #pragma unroll 2
    for (int d = t; d < DD; d += 256) {
        float mk = mrow[d];
        float p  = prow[d];
        float m2 = mk * mk;
        g_B1[(size_t)bm * DD + d] = __float2bfloat16(m2);
        g_B2[(size_t)bm * DD + d] = __float2bfloat16(-2.0f * m2 * p);
        float mp = mk * p;
        psum += mp * mp;
    }

    __shared__ float red[256];
    red[t] = psum;
    __syncthreads();
    #pragma unroll
    for (int s = 128; s > 0; s >>= 1) {
        if (t < s) red[t] += red[t + s];
        __syncthreads();
    }
    if (t == 0) g_pterm[bm] = red[0];
}

// ---------------------------------------------------------------------------
// Main: fused dual-GEMM logits via mma.sync bf16.
// grid = (NQ/NROWS, BS) = (16, 8); block = 256 threads (8 warps, 4x2).
// Warp tile: 32 rows x 32 cols. Accumulator: acc[2 mtiles][4 ntiles][4].
// ---------------------------------------------------------------------------
__global__ __launch_bounds__(256, 1)
void proto_logits_kernel(const float* __restrict__ q,
                         const float* __restrict__ scale,
                         float* __restrict__ out) {
    __shared__ __align__(16) __nv_bfloat16 sQ2[NROWS * ASTRIDE];
    __shared__ __align__(16) __nv_bfloat16 sQ [NROWS * ASTRIDE];
    __shared__ __align__(16) __nv_bfloat16 sB1[MP * ASTRIDE];
    __shared__ __align__(16) __nv_bfloat16 sB2[MP * ASTRIDE];
    __shared__ float sPterm[MP];

    const int b    = blockIdx.y;
    const int n0   = blockIdx.x * NROWS;
    const int t    = threadIdx.x;
    const int warp = t >> 5;
    const int lane = t & 31;
    const int wm   = warp >> 1;     // 0..3 : row group of 32
    const int wn   = warp & 1;      // 0..1 : col group of 32
    const int gid  = lane >> 2;     // groupID  (0..7)
    const int tig  = lane & 3;      // thread-in-group (0..3)

    if (t < MP) sPterm[t] = g_pterm[b * MP + t];

    float acc[2][4][4];
    #pragma unroll
    for (int i = 0; i < 2; i++)
        #pragma unroll
        for (int j = 0; j < 4; j++)
            #pragma unroll
            for (int k = 0; k < 4; k++) acc[i][j][k] = 0.f;

    const float*         qbase  = q    + ((size_t)b * NQ + n0) * DD;
    const __nv_bfloat16* B1base = g_B1 + (size_t)b * MP * DD;
    const __nv_bfloat16* B2base = g_B2 + (size_t)b * MP * DD;

    for (int d0 = 0; d0 < DD; d0 += KC) {
        // --- stage q chunk: 128 rows x 32 floats = 1024 float4; 4 per thread
        #pragma unroll
        for (int i = 0; i < 4; i++) {
            int idx = t + i * 256;          // 0..1023
            int row = idx >> 3;
            int c4  = idx & 7;
            float4 v = *(const float4*)(qbase + (size_t)row * DD + d0 + c4 * 4);
            int so = row * ASTRIDE + c4 * 4;
            sQ [so + 0] = __float2bfloat16(v.x);
            sQ [so + 1] = __float2bfloat16(v.y);
            sQ [so + 2] = __float2bfloat16(v.z);
            sQ [so + 3] = __float2bfloat16(v.w);
            sQ2[so + 0] = __float2bfloat16(v.x * v.x);
            sQ2[so + 1] = __float2bfloat16(v.y * v.y);
            sQ2[so + 2] = __float2bfloat16(v.z * v.z);
            sQ2[so + 3] = __float2bfloat16(v.w * v.w);
        }
        // --- stage B chunks: 64 rows x 32 bf16 each = 256 uint4 per matrix
        {
            int row = t >> 2;               // 0..63
            int c8  = t & 3;                // 0..3 (8 bf16 = 16B each)
            uint4 v1 = *((const uint4*)(B1base + (size_t)row * DD + d0) + c8);
            uint4 v2 = *((const uint4*)(B2base + (size_t)row * DD + d0) + c8);
            *(uint4*)(&sB1[row * ASTRIDE + c8 * 8]) = v1;
            *(uint4*)(&sB2[row * ASTRIDE + c8 * 8]) = v2;
        }
        __syncthreads();

        // --- compute: 2 passes (q^2*B1, q*B2), KC/16 k-steps each
        #pragma unroll
        for (int pass = 0; pass < 2; pass++) {
            const __nv_bfloat16* A  = pass ? sQ  : sQ2;
            const __nv_bfloat16* Bm = pass ? sB2 : sB1;
            #pragma unroll
            for (int kk = 0; kk < KC; kk += 16) {
                uint32_t af[2][4];
                #pragma unroll
                for (int mt = 0; mt < 2; mt++) {
                    int r = wm * 32 + mt * 16 + gid;
                    const __nv_bfloat16* base = A + r * ASTRIDE + kk + tig * 2;
                    af[mt][0] = *(const uint32_t*)(base);
                    af[mt][1] = *(const uint32_t*)(base + 8 * ASTRIDE);
                    af[mt][2] = *(const uint32_t*)(base + 8);
                    af[mt][3] = *(const uint32_t*)(base + 8 * ASTRIDE + 8);
                }
                uint32_t bfr[4][2];
                #pragma unroll
                for (int nt = 0; nt < 4; nt++) {
                    int nn = wn * 32 + nt * 8 + gid;
                    const __nv_bfloat16* base = Bm + nn * ASTRIDE + kk + tig * 2;
                    bfr[nt][0] = *(const uint32_t*)(base);
                    bfr[nt][1] = *(const uint32_t*)(base + 8);
                }
                #pragma unroll
                for (int mt = 0; mt < 2; mt++)
                    #pragma unroll
                    for (int nt = 0; nt < 4; nt++) {
                        asm volatile(
                            "mma.sync.aligned.m16n8k16.row.col.f32.bf16.bf16.f32 "
                            "{%0,%1,%2,%3}, {%4,%5,%6,%7}, {%8,%9}, {%0,%1,%2,%3};\n"
                            : "+f"(acc[mt][nt][0]), "+f"(acc[mt][nt][1]),
                              "+f"(acc[mt][nt][2]), "+f"(acc[mt][nt][3])
                            : "r"(af[mt][0]), "r"(af[mt][1]),
                              "r"(af[mt][2]), "r"(af[mt][3]),
                              "r"(bfr[nt][0]), "r"(bfr[nt][1]));
                    }
            }
        }
        __syncthreads();
    }

    // --- epilogue: out = scale/D * (acc + pterm[col])
    const float s = scale[0] * (1.0f / (float)DD);
    float* obase = out + ((size_t)b * NQ + n0) * MP;
    #pragma unroll
    for (int mt = 0; mt < 2; mt++) {
        #pragma unroll
        for (int nt = 0; nt < 4; nt++) {
            int r0 = wm * 32 + mt * 16 + gid;
            int c0 = wn * 32 + nt * 8 + tig * 2;
            float p0 = sPterm[c0];
            float p1 = sPterm[c0 + 1];
            float2 o01 = make_float2(s * (acc[mt][nt][0] + p0),
                                     s * (acc[mt][nt][1] + p1));
            float2 o23 = make_float2(s * (acc[mt][nt][2] + p0),
                                     s * (acc[mt][nt][3] + p1));
            *(float2*)(obase + (size_t)r0 * MP + c0)       = o01;
            *(float2*)(obase + (size_t)(r0 + 8) * MP + c0) = o23;
        }
    }
}

// ---------------------------------------------------------------------------
// Launch. Inputs (metadata order): 0=prototypes [8,64,1024] f32,
// 1=masktypes [8,64,1024] f32, 2=query [8,2048,1024] f32, 3=support,
// 4=support_labels, 5=scale [1] f32, (n_way/n_shot unused).
// Output: [8,2048,64] f32.
// ---------------------------------------------------------------------------
extern "C" void kernel_launch(void* const* d_in, const int* in_sizes, int n_in,
                              void* d_out, int out_size) {
    const float* proto = (const float*)d_in[0];
    const float* mask  = (const float*)d_in[1];
    const float* query = (const float*)d_in[2];
    const float* scale = (const float*)d_in[5];
    float* out = (float*)d_out;

    proto_prep_kernel<<<BS * MP, 256>>>(proto, mask);
    dim3 grid(NQ / NROWS, BS);
    proto_logits_kernel<<<grid, 256>>>(query, scale, out);
}

// round 2
// speedup vs baseline: 1.3675x; 1.3675x over previous
#include <cuda_runtime.h>
#include <cuda_bf16.h>
#include <cstdint>

// Problem constants (fixed by the dataset)
#define BS 8
#define NQ 2048
#define MP 64
#define DD 1024

// Tiling
#define KC 32                  // K-chunk (d elems) per stage
#define NCHUNKS (DD / KC)      // 32
#define ASTRIDE 40             // KC + 8 pad (bf16) -> conflict-free LDS.32
#define NROWS 128              // CTA rows (N tile)

// __device__ scratch (allocation-free rule)
__device__ __nv_bfloat16 g_B1[BS * MP * DD];   // mask^2
__device__ __nv_bfloat16 g_B2[BS * MP * DD];   // -2 * mask^2 * p
__device__ float         g_pterm[BS * MP];     // sum_d (mask*p)^2

// ---------------------------------------------------------------------------
// Prep kernel (unchanged): build bf16 B matrices + pterm.
// ---------------------------------------------------------------------------
__global__ void proto_prep_kernel(const float* __restrict__ proto,
                                  const float* __restrict__ mask) {
    const int bm = blockIdx.x;
    const int t  = threadIdx.x;
    const float* mrow = mask  + (size_t)bm * DD;
    const float* prow = proto + (size_t)bm * DD;

    float psum = 0.f;
    #pragma unroll 2
    for (int d = t; d < DD; d += 256) {
        float mk = mrow[d];
        float p  = prow[d];
        float m2 = mk * mk;
        g_B1[(size_t)bm * DD + d] = __float2bfloat16(m2);
        g_B2[(size_t)bm * DD + d] = __float2bfloat16(-2.0f * m2 * p);
        float mp = mk * p;
        psum += mp * mp;
    }
    __shared__ float red[256];
    red[t] = psum;
    __syncthreads();
    #pragma unroll
    for (int s = 128; s > 0; s >>= 1) {
        if (t < s) red[t] += red[t + s];
        __syncthreads();
    }
    if (t == 0) g_pterm[bm] = red[0];
}

// ---------------------------------------------------------------------------
// Helpers
// ---------------------------------------------------------------------------
__device__ __forceinline__ void cp_async16(void* smem_dst, const void* gmem_src) {
    uint32_t s = (uint32_t)__cvta_generic_to_shared(smem_dst);
    asm volatile("cp.async.cg.shared.global [%0], [%1], 16;\n" :: "r"(s), "l"(gmem_src));
}
__device__ __forceinline__ uint32_t sq_bf16x2(uint32_t x) {
    __nv_bfloat162 v = *reinterpret_cast<__nv_bfloat162*>(&x);
    __nv_bfloat162 r = __hmul2(v, v);
    return *reinterpret_cast<uint32_t*>(&r);
}

// ---------------------------------------------------------------------------
// Main kernel: pipelined fused dual-GEMM.
// grid = (16, 8), block = 256 (8 warps, 4x2), warp tile 32x32.
// ---------------------------------------------------------------------------
__global__ __launch_bounds__(256, 1)
void proto_logits_kernel(const float* __restrict__ q,
                         const float* __restrict__ scale,
                         float* __restrict__ out) {
    __shared__ __align__(16) __nv_bfloat16 sQ [2][NROWS * ASTRIDE]; // 20.0 KB
    __shared__ __align__(16) __nv_bfloat16 sB1[2][MP * ASTRIDE];    // 10.0 KB
    __shared__ __align__(16) __nv_bfloat16 sB2[2][MP * ASTRIDE];    // 10.0 KB
    __shared__ float sPterm[MP];

    const int b    = blockIdx.y;
    const int n0   = blockIdx.x * NROWS;
    const int t    = threadIdx.x;
    const int warp = t >> 5;
    const int lane = t & 31;
    const int wm   = warp >> 1;
    const int wn   = warp & 1;
    const int gid  = lane >> 2;
    const int tig  = lane & 3;

    if (t < MP) sPterm[t] = g_pterm[b * MP + t];

    float acc[2][4][4];
    #pragma unroll
    for (int i = 0; i < 2; i++)
        #pragma unroll
        for (int j = 0; j < 4; j++)
            #pragma unroll
            for (int k = 0; k < 4; k++) acc[i][j][k] = 0.f;

    const float*         qbase  = q    + ((size_t)b * NQ + n0) * DD;
    const __nv_bfloat16* B1base = g_B1 + (size_t)b * MP * DD;
    const __nv_bfloat16* B2base = g_B2 + (size_t)b * MP * DD;

    // q-staging decomposition: idx = t + 256*j, row = idx>>3, c4 = idx&7
    const int q_row0 = t >> 3;          // rows handled: q_row0 + 32*j
    const int q_c4   = t & 7;

    // B cp.async decomposition: each thread does 2 ops per matrix
    const int b_row0 = t >> 2;          // op rows: b_row0 (t<256 covers 0..63)
    const int b_c16  = t & 3;           // 16B column group

    float4 qr[4];

    // ---- prologue: issue B_0, LDG q_0
    {
        const __nv_bfloat16* s1 = B1base + (size_t)b_row0 * DD + b_c16 * 8;
        const __nv_bfloat16* s2 = B2base + (size_t)b_row0 * DD + b_c16 * 8;
        cp_async16(&sB1[0][b_row0 * ASTRIDE + b_c16 * 8], s1);
        cp_async16(&sB2[0][b_row0 * ASTRIDE + b_c16 * 8], s2);
        asm volatile("cp.async.commit_group;\n");
        #pragma unroll
        for (int j = 0; j < 4; j++)
            qr[j] = *(const float4*)(qbase + (size_t)(q_row0 + 32 * j) * DD + q_c4 * 4);
    }

    for (int i = 0; i < NCHUNKS; ++i) {
        const int buf = i & 1;

        // store q_i (fp32 regs -> bf16 smem)
        #pragma unroll
        for (int j = 0; j < 4; j++) {
            int so = (q_row0 + 32 * j) * ASTRIDE + q_c4 * 4;
            __nv_bfloat162 lo = __floats2bfloat162_rn(qr[j].x, qr[j].y);
            __nv_bfloat162 hi = __floats2bfloat162_rn(qr[j].z, qr[j].w);
            *(uint32_t*)(&sQ[buf][so + 0]) = *reinterpret_cast<uint32_t*>(&lo);
            *(uint32_t*)(&sQ[buf][so + 2]) = *reinterpret_cast<uint32_t*>(&hi);
        }
        asm volatile("cp.async.wait_group 0;\n");
        __syncthreads();

        // issue next stage loads (overlap with compute below)
        if (i + 1 < NCHUNKS) {
            const int d1 = (i + 1) * KC;
            const __nv_bfloat16* s1 = B1base + (size_t)b_row0 * DD + d1 + b_c16 * 8;
            const __nv_bfloat16* s2 = B2base + (size_t)b_row0 * DD + d1 + b_c16 * 8;
            cp_async16(&sB1[buf ^ 1][b_row0 * ASTRIDE + b_c16 * 8], s1);
            cp_async16(&sB2[buf ^ 1][b_row0 * ASTRIDE + b_c16 * 8], s2);
            asm volatile("cp.async.commit_group;\n");
            #pragma unroll
            for (int j = 0; j < 4; j++)
                qr[j] = *(const float4*)(qbase + (size_t)(q_row0 + 32 * j) * DD + d1 + q_c4 * 4);
        }

        // compute chunk i
        #pragma unroll
        for (int kk = 0; kk < KC; kk += 16) {
            uint32_t aq[2][4], aq2[2][4];
            #pragma unroll
            for (int mt = 0; mt < 2; mt++) {
                int r = wm * 32 + mt * 16 + gid;
                const __nv_bfloat16* base = &sQ[buf][r * ASTRIDE + kk + tig * 2];
                aq[mt][0] = *(const uint32_t*)(base);
                aq[mt][1] = *(const uint32_t*)(base + 8 * ASTRIDE);
                aq[mt][2] = *(const uint32_t*)(base + 8);
                aq[mt][3] = *(const uint32_t*)(base + 8 * ASTRIDE + 8);
                #pragma unroll
                for (int r4 = 0; r4 < 4; r4++) aq2[mt][r4] = sq_bf16x2(aq[mt][r4]);
            }
            uint32_t b1f[4][2], b2f[4][2];
            #pragma unroll
            for (int nt = 0; nt < 4; nt++) {
                int nn = wn * 32 + nt * 8 + gid;
                const __nv_bfloat16* p1 = &sB1[buf][nn * ASTRIDE + kk + tig * 2];
                const __nv_bfloat16* p2 = &sB2[buf][nn * ASTRIDE + kk + tig * 2];
                b1f[nt][0] = *(const uint32_t*)(p1);
                b1f[nt][1] = *(const uint32_t*)(p1 + 8);
                b2f[nt][0] = *(const uint32_t*)(p2);
                b2f[nt][1] = *(const uint32_t*)(p2 + 8);
            }
            #pragma unroll
            for (int mt = 0; mt < 2; mt++)
                #pragma unroll
                for (int nt = 0; nt < 4; nt++) {
                    asm volatile(
                        "mma.sync.aligned.m16n8k16.row.col.f32.bf16.bf16.f32 "
                        "{%0,%1,%2,%3}, {%4,%5,%6,%7}, {%8,%9}, {%0,%1,%2,%3};\n"
                        : "+f"(acc[mt][nt][0]), "+f"(acc[mt][nt][1]),
                          "+f"(acc[mt][nt][2]), "+f"(acc[mt][nt][3])
                        : "r"(aq2[mt][0]), "r"(aq2[mt][1]),
                          "r"(aq2[mt][2]), "r"(aq2[mt][3]),
                          "r"(b1f[nt][0]), "r"(b1f[nt][1]));
                    asm volatile(
                        "mma.sync.aligned.m16n8k16.row.col.f32.bf16.bf16.f32 "
                        "{%0,%1,%2,%3}, {%4,%5,%6,%7}, {%8,%9}, {%0,%1,%2,%3};\n"
                        : "+f"(acc[mt][nt][0]), "+f"(acc[mt][nt][1]),
                          "+f"(acc[mt][nt][2]), "+f"(acc[mt][nt][3])
                        : "r"(aq[mt][0]), "r"(aq[mt][1]),
                          "r"(aq[mt][2]), "r"(aq[mt][3]),
                          "r"(b2f[nt][0]), "r"(b2f[nt][1]));
                }
        }
    }

    // ---- epilogue: out = scale/D * (acc + pterm[col])
    const float s = scale[0] * (1.0f / (float)DD);
    float* obase = out + ((size_t)b * NQ + n0) * MP;
    #pragma unroll
    for (int mt = 0; mt < 2; mt++) {
        #pragma unroll
        for (int nt = 0; nt < 4; nt++) {
            int r0 = wm * 32 + mt * 16 + gid;
            int c0 = wn * 32 + nt * 8 + tig * 2;
            float p0 = sPterm[c0];
            float p1 = sPterm[c0 + 1];
            float2 o01 = make_float2(s * (acc[mt][nt][0] + p0),
                                     s * (acc[mt][nt][1] + p1));
            float2 o23 = make_float2(s * (acc[mt][nt][2] + p0),
                                     s * (acc[mt][nt][3] + p1));
            *(float2*)(obase + (size_t)r0 * MP + c0)       = o01;
            *(float2*)(obase + (size_t)(r0 + 8) * MP + c0) = o23;
        }
    }
}

// ---------------------------------------------------------------------------
// Launch. Inputs: 0=prototypes, 1=masktypes, 2=query, 3=support,
// 4=support_labels, 5=scale. Output: [8,2048,64] f32.
// ---------------------------------------------------------------------------
extern "C" void kernel_launch(void* const* d_in, const int* in_sizes, int n_in,
                              void* d_out, int out_size) {
    const float* proto = (const float*)d_in[0];
    const float* mask  = (const float*)d_in[1];
    const float* query = (const float*)d_in[2];
    const float* scale = (const float*)d_in[5];
    float* out = (float*)d_out;

    proto_prep_kernel<<<BS * MP, 256>>>(proto, mask);
    dim3 grid(NQ / NROWS, BS);
    proto_logits_kernel<<<grid, 256>>>(query, scale, out);
}